// round 10
// baseline (speedup 1.0000x reference)
#include <cuda_runtime.h>

#define H 64
#define KCH 24
#define THREADS 256
#define NTAPS_MAX (KCH * 25)

// ---------------------------------------------------------------------------
// One CTA per batch b. Builds the (channel-independent) tap list once, then
// loops over the 24 output channels: zero smem map -> scatter taps with the
// channel's weights -> stream out 16KB with coalesced float4 streaming stores.
// ---------------------------------------------------------------------------
__global__ __launch_bounds__(THREADS)
void gauss_batch_kernel(const float* __restrict__ x,
                        const float* __restrict__ weight,
                        const int*  __restrict__ vis_batch,
                        const int*  __restrict__ vis_kps,
                        int n_vis,
                        float* __restrict__ out)
{
    const int b   = blockIdx.x;   // batch 0..1023
    const int tid = threadIdx.x;

    __shared__ float map[H * H];            // 16 KB accumulation map
    __shared__ float wch[KCH * 25];         // current channel's 600 weights
    __shared__ int   taps[NTAPS_MAX];       // packed: (pix<<10) | widx
    __shared__ int   pxS[KCH], pyS[KCH], actS[KCH];
    __shared__ int   killS[KCH];
    __shared__ int   ntapsS;

    if (tid == 0)  ntapsS = 0;
    if (tid < KCH) killS[tid] = 0;
    __syncthreads();

    // vis-kill scan: 256 entries, 1/thread (1KB tables, L2-hot)
    for (int i = tid; i < n_vis; i += THREADS)
        if (__ldg(&vis_batch[i]) == b) killS[__ldg(&vis_kps[i])] = 1;
    __syncthreads();

    // coords + torch quirk + invalid masking (once per batch)
    if (tid < KCH) {
        float fx = __ldg(&x[((size_t)b * KCH + tid) * 2 + 0]);
        float fy = __ldg(&x[((size_t)b * KCH + tid) * 2 + 1]);
        // match JAX: round(((x+1)*0.5)*(H-1)), banker's rounding
        int cx = (int)rintf(((fx + 1.0f) * 0.5f) * (float)(H - 1));
        int cy = (int)rintf(((fy + 1.0f) * 0.5f) * (float)(H - 1));
        // invalid -> coords zeroed -> cx==0 -> inactive; quirk: cx != 0 required
        pxS[tid]  = cx;
        pyS[tid]  = cy;
        actS[tid] = ((unsigned)cx < (unsigned)H) && ((unsigned)cy < (unsigned)H)
                    && (cx != 0) && (!killS[tid]);
    }
    __syncthreads();

    // build compacted tap list (channel-independent).
    // lax conv = cross-correlation: out[yk+2-dy, xk+2-dx] += w[o, k, dy, dx]
    // flat build index it == widx == k*25 + dy*5 + dx.
    for (int it = tid; it < NTAPS_MAX; it += THREADS) {
        int k = it / 25;
        if (actS[k]) {
            int t  = it - k * 25;
            int dy = t / 5;
            int dx = t - dy * 5;
            int yy = pyS[k] + 2 - dy;
            int xx = pxS[k] + 2 - dx;
            if ((unsigned)yy < (unsigned)H && (unsigned)xx < (unsigned)H) {
                int s = atomicAdd(&ntapsS, 1);
                taps[s] = ((yy * H + xx) << 10) | it;
            }
        }
    }
    __syncthreads();
    const int nt = ntapsS;

    float4* __restrict__ mapv = (float4*)map;
    const float4 z4 = make_float4(0.f, 0.f, 0.f, 0.f);

    // ---- per-channel loop ----
    for (int o = 0; o < KCH; o++) {
        // phase A: zero map + preload this channel's weights (600 floats)
        #pragma unroll
        for (int i = 0; i < 4; i++) mapv[(i << 8) + tid] = z4;
        if (tid < 150)
            ((float4*)wch)[tid] =
                __ldg(&((const float4*)(weight + (size_t)o * (KCH * 25)))[tid]);
        __syncthreads();

        // phase B: scatter (~2 iterations/thread, spread-address smem atomics)
        for (int it = tid; it < nt; it += THREADS) {
            int v = taps[it];
            atomicAdd(&map[v >> 10], wch[v & 1023]);
        }
        __syncthreads();

        // phase C: stream out 16KB — 4 fully-coalesced 512B/warp STG.128
        float4* __restrict__ dst = (float4*)(out + (((size_t)b * KCH + o) << 12));
        #pragma unroll
        for (int i = 0; i < 4; i++)
            __stcs(&dst[(i << 8) + tid], mapv[(i << 8) + tid]);
        __syncthreads();   // protect map before next channel's zero
    }
}

extern "C" void kernel_launch(void* const* d_in, const int* in_sizes, int n_in,
                              void* d_out, int out_size)
{
    const float* x      = (const float*)d_in[0];
    const float* weight = (const float*)d_in[1];
    const int*   vb     = (const int*)d_in[2];
    const int*   vk     = (const int*)d_in[3];
    float*       out    = (float*)d_out;

    int n_vis = in_sizes[2];
    int B     = in_sizes[0] / (KCH * 2);   // 1024

    gauss_batch_kernel<<<B, THREADS>>>(x, weight, vb, vk, n_vis, out);
}